// round 1
// baseline (speedup 1.0000x reference)
#include <cuda_runtime.h>
#include <math.h>

#define Nn      65536
#define Mm      256
#define Hh      4
#define CTRLD   1024
#define INDIM   2048
#define LSTMIN  3072
#define OUTD    2048
#define EPSF    1e-8f

// ---------------- scratch (__device__ globals; no allocation allowed) ----------
__device__ float g_mem[(size_t)Nn * Mm];   // working copy of memory (64MB)
__device__ float g_simw[Nn];               // cosine sim for pending WRITE head
__device__ float g_simr[Nn];               // cosine sim for pending READ head
__device__ float g_wsh[Nn];                // sharpened (unnormalized) weights
__device__ float g_gates[3 * CTRLD];       // i, f, g gates (o gate unused)
__device__ float g_ctrl[CTRLD];            // controller cell state c
__device__ float g_o[Hh * 1036];           // head FC outputs: [774 write | 262 read] per head
__device__ float g_kw[Hh * Mm];            // write keys (tanh)
__device__ float g_kr[Hh * Mm];            // read keys (tanh)
__device__ float g_e [Hh * Mm];            // erase vectors (sigmoid)
__device__ float g_a [Hh * Mm];            // add vectors (tanh)
__device__ float g_sc[80];                 // per (head,role): beta,g,s0,s1,s2,gamma,knorm,pad
__device__ float g_S [32];                 // accumulators: per head: S1w,S2w,S1r,S2r
__device__ float g_reads[Hh * Mm];         // read vectors

// ---------------- helpers ----------------
__device__ __forceinline__ float warpSum(float v) {
#pragma unroll
    for (int o = 16; o; o >>= 1) v += __shfl_down_sync(0xffffffffu, v, o);
    return v;
}
__device__ __forceinline__ float blockSum(float v) {
    __shared__ float sh[32];
    int lane = threadIdx.x & 31, wid = threadIdx.x >> 5;
    v = warpSum(v);
    if (lane == 0) sh[wid] = v;
    __syncthreads();
    int nw = (blockDim.x + 31) >> 5;
    v = (threadIdx.x < nw) ? sh[threadIdx.x] : 0.f;
    if (wid == 0) v = warpSum(v);
    return v;
}
__device__ __forceinline__ float sigmoidf(float x) { return 1.f / (1.f + expf(-x)); }
__device__ __forceinline__ float softplusf(float x) {
    return x > 0.f ? x + log1pf(expf(-x)) : log1pf(expf(x));
}

// ---------------- 1) LSTM gates GEMV (only i,f,g chunks; o gate unused) --------
__global__ void __launch_bounds__(128) k_gates(
    const float* __restrict__ x, const float* __restrict__ prev_reads,
    const float* __restrict__ prev_h, const float* __restrict__ W_ih,
    const float* __restrict__ W_hh, const float* __restrict__ b_lstm) {
    int row = blockIdx.x;          // 0..3071
    int t = threadIdx.x;
    const float4* wa = (const float4*)(W_ih + (size_t)row * LSTMIN);
    const float4* xb = (const float4*)x;
    const float4* rb = (const float4*)prev_reads;
    const float4* wh = (const float4*)(W_hh + (size_t)row * CTRLD);
    const float4* hb = (const float4*)prev_h;
    float s = 0.f;
#pragma unroll 4
    for (int j = t; j < 512; j += 128) { float4 a = wa[j], v = xb[j]; s += a.x*v.x + a.y*v.y + a.z*v.z + a.w*v.w; }
#pragma unroll 2
    for (int j = t; j < 256; j += 128) { float4 a = wa[512 + j], v = rb[j]; s += a.x*v.x + a.y*v.y + a.z*v.z + a.w*v.w; }
#pragma unroll 2
    for (int j = t; j < 256; j += 128) { float4 a = wh[j], v = hb[j]; s += a.x*v.x + a.y*v.y + a.z*v.z + a.w*v.w; }
    s = blockSum(s);
    if (t == 0) g_gates[row] = s + b_lstm[row];
}

// ---------------- 2) cell state + zero accumulators ----------------------------
__global__ void k_ctrl(const float* __restrict__ prev_c) {
    int j = threadIdx.x;   // 1024 threads
    float ig = g_gates[j], fg = g_gates[CTRLD + j], gg = g_gates[2 * CTRLD + j];
    g_ctrl[j] = sigmoidf(fg) * prev_c[j] + sigmoidf(ig) * tanhf(gg);
    g_reads[j] = 0.f;
    if (j < 32) g_S[j] = 0.f;
}

// ---------------- 3) all head FCs: ow = Ww@ctrl+bw, orr = Wr@ctrl+br ------------
__global__ void __launch_bounds__(128) k_headfc(
    const float* __restrict__ Ww, const float* __restrict__ bw,
    const float* __restrict__ Wr, const float* __restrict__ br) {
    int row = blockIdx.x;              // 0..4143
    int hd = row / 1036, k = row % 1036;
    const float* wrow; float bias;
    if (k < 774) { wrow = Ww + ((size_t)hd * 774 + k) * CTRLD; bias = bw[hd * 774 + k]; }
    else         { int kk = k - 774; wrow = Wr + ((size_t)hd * 262 + kk) * CTRLD; bias = br[hd * 262 + kk]; }
    const float4* w4 = (const float4*)wrow;
    const float4* c4 = (const float4*)g_ctrl;
    int t = threadIdx.x; float s = 0.f;
#pragma unroll 2
    for (int j = t; j < 256; j += 128) { float4 a = w4[j], v = c4[j]; s += a.x*v.x + a.y*v.y + a.z*v.z + a.w*v.w; }
    s = blockSum(s);
    if (t == 0) g_o[row] = s + bias;
}

// ---------------- 4) derive keys / scalars / erase / add -----------------------
__global__ void __launch_bounds__(256) k_derive() {
    int b = blockIdx.x; int hd = b >> 1; int role = b & 1;   // role 0=write 1=read
    const float* o = g_o + hd * 1036 + (role ? 774 : 0);
    int t = threadIdx.x;
    float kv = tanhf(o[t]);
    (role ? g_kr : g_kw)[hd * Mm + t] = kv;
    if (!role) {
        g_e[hd * Mm + t] = sigmoidf(o[262 + t]);
        g_a[hd * Mm + t] = tanhf(o[518 + t]);
    }
    float ss = blockSum(kv * kv);
    if (t == 0) {
        float* sc = g_sc + b * 8;
        sc[0] = softplusf(o[256]);          // beta
        sc[1] = sigmoidf(o[257]);           // g
        float s0 = o[258], s1 = o[259], s2 = o[260];
        float mx = fmaxf(s0, fmaxf(s1, s2));
        float e0 = expf(s0 - mx), e1 = expf(s1 - mx), e2 = expf(s2 - mx);
        float es = e0 + e1 + e2;
        sc[2] = e0 / es; sc[3] = e1 / es; sc[4] = e2 / es;   // shift softmax
        sc[5] = 1.f + softplusf(o[261]);    // gamma
        sc[6] = sqrtf(ss);                  // ||k||
    }
}

// ---------------- 5) pass 0: sim for head-0 write key + exp-sum -----------------
__global__ void __launch_bounds__(256) k_pass0(const float* __restrict__ mem) {
    int gid = blockIdx.x * blockDim.x + threadIdx.x;
    int r = gid >> 5, lane = gid & 31;
    const float4* row = (const float4*)(mem + (size_t)r * Mm);
    const float4* k4  = (const float4*)g_kw;   // head-0 write key
    float dot = 0.f, ss = 0.f;
#pragma unroll
    for (int j = 0; j < 2; j++) {
        int idx = lane + 32 * j;
        float4 m = row[idx], kk = k4[idx];
        dot += m.x*kk.x + m.y*kk.y + m.z*kk.z + m.w*kk.w;
        ss  += m.x*m.x + m.y*m.y + m.z*m.z + m.w*m.w;
    }
    dot = warpSum(dot); ss = warpSum(ss);
    __shared__ float shexp[8];
    if (lane == 0) {
        float sim = dot / (sqrtf(ss) * g_sc[6] + EPSF);
        g_simw[r] = sim;
        shexp[threadIdx.x >> 5] = expf(g_sc[0] * sim);
    }
    __syncthreads();
    if (threadIdx.x == 0) {
        float s = 0.f;
#pragma unroll
        for (int w = 0; w < 8; w++) s += shexp[w];
        atomicAdd(&g_S[0], s);
    }
}

// ---------------- 6) addressing pass B: interpolate + shift + sharpen -----------
__global__ void __launch_bounds__(256) k_addrB(
    const float* __restrict__ prevw, int use_r, int sc_base, int s1, int s2) {
    int i = blockIdx.x * blockDim.x + threadIdx.x;
    const float* sim = use_r ? g_simr : g_simw;
    const float* sc = g_sc + sc_base;
    float beta = sc[0], gg = sc[1], c0 = sc[2], c1 = sc[3], c2 = sc[4], gamma = sc[5];
    float gInvS1 = gg / g_S[s1];
    float om = 1.f - gg;
    int ip = (i + 1) & (Nn - 1), im = (i - 1) & (Nn - 1);
    float wgp = gInvS1 * expf(beta * sim[ip]) + om * prevw[ip];
    float wgc = gInvS1 * expf(beta * sim[i])  + om * prevw[i];
    float wgm = gInvS1 * expf(beta * sim[im]) + om * prevw[im];
    float ws  = c0 * wgp + c1 * wgc + c2 * wgm;
    float wsh = powf(fmaxf(ws, 1e-12f), gamma);
    g_wsh[i] = wsh;
    float v = blockSum(wsh);
    if (threadIdx.x == 0) atomicAdd(&g_S[s2], v);
}

// ---------------- 7) memory update + read-sim + next-write-sim + norms ----------
__global__ void __launch_bounds__(256) k_update(const float* __restrict__ mem_in, int hd) {
    int gid = blockIdx.x * blockDim.x + threadIdx.x;
    int r = gid >> 5, lane = gid & 31;
    const float* src = (hd == 0) ? mem_in : g_mem;
    float w = g_wsh[r] / (g_S[hd * 4 + 1] + EPSF);
    const float4* row4 = (const float4*)(src + (size_t)r * Mm);
    float4* dst4 = (float4*)(g_mem + (size_t)r * Mm);
    const float4* e4  = (const float4*)(g_e  + hd * Mm);
    const float4* a4  = (const float4*)(g_a  + hd * Mm);
    const float4* kr4 = (const float4*)(g_kr + hd * Mm);
    const float4* kw4 = (const float4*)(g_kw + ((hd + 1) & 3) * Mm);
    float dr = 0.f, dw = 0.f, ss = 0.f;
#pragma unroll
    for (int j = 0; j < 2; j++) {
        int idx = lane + 32 * j;
        float4 m = row4[idx], ee = e4[idx], aa = a4[idx];
        float4 nm;
        nm.x = m.x * (1.f - w * ee.x) + w * aa.x;
        nm.y = m.y * (1.f - w * ee.y) + w * aa.y;
        nm.z = m.z * (1.f - w * ee.z) + w * aa.z;
        nm.w = m.w * (1.f - w * ee.w) + w * aa.w;
        dst4[idx] = nm;
        float4 kk = kr4[idx];
        dr += nm.x*kk.x + nm.y*kk.y + nm.z*kk.z + nm.w*kk.w;
        ss += nm.x*nm.x + nm.y*nm.y + nm.z*nm.z + nm.w*nm.w;
        float4 kw = kw4[idx];
        dw += nm.x*kw.x + nm.y*kw.y + nm.z*kw.z + nm.w*kw.w;
    }
    dr = warpSum(dr); dw = warpSum(dw); ss = warpSum(ss);
    __shared__ float shr[8], shw[8];
    float beta_r  = g_sc[(hd * 2 + 1) * 8 + 0];
    float kn_r    = g_sc[(hd * 2 + 1) * 8 + 6];
    float beta_wn = g_sc[((hd + 1) * 2) * 8 + 0];   // g_sc sized 80 so hd=3 read is safe
    float kn_wn   = g_sc[((hd + 1) * 2) * 8 + 6];
    if (lane == 0) {
        float nrm = sqrtf(ss);
        float simr = dr / (nrm * kn_r + EPSF);
        g_simr[r] = simr;
        shr[threadIdx.x >> 5] = expf(beta_r * simr);
        if (hd < 3) {
            float simw = dw / (nrm * kn_wn + EPSF);
            g_simw[r] = simw;
            shw[threadIdx.x >> 5] = expf(beta_wn * simw);
        }
    }
    __syncthreads();
    if (threadIdx.x == 0) {
        float sr = 0.f, sw = 0.f;
#pragma unroll
        for (int k = 0; k < 8; k++) { sr += shr[k]; if (hd < 3) sw += shw[k]; }
        atomicAdd(&g_S[hd * 4 + 2], sr);
        if (hd < 3) atomicAdd(&g_S[(hd + 1) * 4 + 0], sw);
    }
}

// ---------------- 8) read vector: reads[hd] = rw @ mem ---------------------------
__global__ void __launch_bounds__(256) k_reads(int hd) {
    int m = threadIdx.x;                        // column 0..255
    float inv = 1.f / (g_S[hd * 4 + 3] + EPSF);
    int rows = Nn / gridDim.x;
    int r0 = blockIdx.x * rows;
    float acc = 0.f;
    for (int r = r0; r < r0 + rows; ++r)
        acc += g_wsh[r] * g_mem[(size_t)r * Mm + m];
    atomicAdd(&g_reads[hd * Mm + m], acc * inv);
}

// ---------------- 9) output GEMV -------------------------------------------------
__global__ void __launch_bounds__(128) k_out(
    const float* __restrict__ W_out, const float* __restrict__ b_out,
    float* __restrict__ out) {
    int row = blockIdx.x, t = threadIdx.x;
    const float4* w4 = (const float4*)(W_out + (size_t)row * (Hh * Mm));
    const float4* r4 = (const float4*)g_reads;
    float s = 0.f;
#pragma unroll 2
    for (int j = t; j < 256; j += 128) { float4 a = w4[j], v = r4[j]; s += a.x*v.x + a.y*v.y + a.z*v.z + a.w*v.w; }
    s = blockSum(s);
    if (t == 0) out[row] = s + b_out[row];
}

// ---------------- launch ----------------------------------------------------------
extern "C" void kernel_launch(void* const* d_in, const int* in_sizes, int n_in,
                              void* d_out, int out_size) {
    const float* x          = (const float*)d_in[0];
    const float* prev_reads = (const float*)d_in[1];
    const float* prev_h     = (const float*)d_in[2];
    const float* prev_c     = (const float*)d_in[3];
    const float* memory     = (const float*)d_in[4];
    const float* prev_rw    = (const float*)d_in[5];
    const float* prev_ww    = (const float*)d_in[6];
    const float* W_ih       = (const float*)d_in[7];
    const float* W_hh       = (const float*)d_in[8];
    const float* b_lstm     = (const float*)d_in[9];
    const float* W_out      = (const float*)d_in[10];
    const float* b_out      = (const float*)d_in[11];
    const float* Ww         = (const float*)d_in[12];
    const float* bw         = (const float*)d_in[13];
    const float* Wr         = (const float*)d_in[14];
    const float* br         = (const float*)d_in[15];
    float* out = (float*)d_out;

    k_gates <<<3072, 128>>>(x, prev_reads, prev_h, W_ih, W_hh, b_lstm);
    k_ctrl  <<<1, 1024>>>(prev_c);
    k_headfc<<<4144, 128>>>(Ww, bw, Wr, br);
    k_derive<<<8, 256>>>();
    k_pass0 <<<Nn / 8, 256>>>(memory);

    for (int hd = 0; hd < 4; ++hd) {
        k_addrB <<<Nn / 256, 256>>>(prev_ww + (size_t)hd * Nn, 0, (hd * 2) * 8,     hd * 4 + 0, hd * 4 + 1);
        k_update<<<Nn / 8, 256>>>(memory, hd);
        k_addrB <<<Nn / 256, 256>>>(prev_rw + (size_t)hd * Nn, 1, (hd * 2 + 1) * 8, hd * 4 + 2, hd * 4 + 3);
        k_reads <<<512, 256>>>(hd);
    }

    k_out<<<OUTD, 128>>>(W_out, b_out, out);
}

// round 2
// speedup vs baseline: 1.0827x; 1.0827x over previous
#include <cuda_runtime.h>
#include <math.h>

#define Nn      65536
#define Mm      256
#define Hh      4
#define CTRLD   1024
#define LSTMIN  3072
#define OUTD    2048
#define EPSF    1e-8f

#define PGRID   512
#define PBLK    256
#define ROWS_B  (Nn / PGRID)      // 128 rows per block
#define ROWS_W  (ROWS_B / 8)      // 16 rows per warp

// ---------------- scratch (__device__ globals) ----------------
__device__ float g_mem[(size_t)Nn * Mm];   // working memory copy (64MB)
__device__ float g_simw[Nn];               // cosine sim, pending WRITE head
__device__ float g_simr[Nn];               // cosine sim, pending READ head
__device__ float g_wshw[Nn];               // sharpened write weights (unnormalized)
__device__ float g_wshr[Nn];               // sharpened read weights (unnormalized)
__device__ float g_gates[3 * CTRLD];
__device__ float g_ctrl[CTRLD];
__device__ float g_o[Hh * 1036];           // [774 write | 262 read] per head
__device__ float g_kw[Hh * Mm];
__device__ float g_kr[Hh * Mm];
__device__ float g_e [Hh * Mm];
__device__ float g_a [Hh * Mm];
__device__ float g_sc[80];                 // per (head,role)*8: beta,g,s0,s1,s2,gamma,knorm,pad
__device__ float g_S [32];                 // per head: S1w,S2w,S1r,S2r
__device__ float g_reads[Hh * Mm];
__device__ unsigned long long g_barcnt;    // monotonic grid-barrier counter
__device__ int g_done_gates;
__device__ int g_done_fc;

// ---------------- helpers ----------------
__device__ __forceinline__ float warpSum(float v) {
#pragma unroll
    for (int o = 16; o; o >>= 1) v += __shfl_down_sync(0xffffffffu, v, o);
    return v;
}
__device__ __forceinline__ float blockSum(float v) {
    __shared__ float sh[32];
    int lane = threadIdx.x & 31, wid = threadIdx.x >> 5;
    v = warpSum(v);
    if (lane == 0) sh[wid] = v;
    __syncthreads();
    int nw = (blockDim.x + 31) >> 5;
    v = (threadIdx.x < nw) ? sh[threadIdx.x] : 0.f;
    if (wid == 0) v = warpSum(v);
    __syncthreads();   // make back-to-back calls safe
    return v;
}
__device__ __forceinline__ float sigmoidf(float x) { return 1.f / (1.f + expf(-x)); }
__device__ __forceinline__ float softplusf(float x) {
    return x > 0.f ? x + log1pf(expf(-x)) : log1pf(expf(x));
}
__device__ __forceinline__ void gridbar(unsigned long long base, int idx) {
    __syncthreads();
    if (threadIdx.x == 0) {
        __threadfence();
        atomicAdd(&g_barcnt, 1ULL);
        unsigned long long target = base + (unsigned long long)idx * gridDim.x;
        while (*(volatile unsigned long long*)&g_barcnt < target) __nanosleep(64);
    }
    __syncthreads();
}

// ---------------- 1) LSTM gates GEMV + (last block) cell state -----------------
__global__ void __launch_bounds__(128) k_gates(
    const float* __restrict__ x, const float* __restrict__ prev_reads,
    const float* __restrict__ prev_h, const float* __restrict__ prev_c,
    const float* __restrict__ W_ih, const float* __restrict__ W_hh,
    const float* __restrict__ b_lstm) {
    int row = blockIdx.x;          // 0..3071 (o gate unused)
    int t = threadIdx.x;
    const float4* wa = (const float4*)(W_ih + (size_t)row * LSTMIN);
    const float4* xb = (const float4*)x;
    const float4* rb = (const float4*)prev_reads;
    const float4* wh = (const float4*)(W_hh + (size_t)row * CTRLD);
    const float4* hb = (const float4*)prev_h;
    float s = 0.f;
#pragma unroll 4
    for (int j = t; j < 512; j += 128) { float4 a = wa[j], v = xb[j]; s += a.x*v.x + a.y*v.y + a.z*v.z + a.w*v.w; }
#pragma unroll 2
    for (int j = t; j < 256; j += 128) { float4 a = wa[512 + j], v = rb[j]; s += a.x*v.x + a.y*v.y + a.z*v.z + a.w*v.w; }
#pragma unroll 2
    for (int j = t; j < 256; j += 128) { float4 a = wh[j], v = hb[j]; s += a.x*v.x + a.y*v.y + a.z*v.z + a.w*v.w; }
    s = blockSum(s);
    __shared__ int s_last;
    if (t == 0) {
        g_gates[row] = s + b_lstm[row];
        __threadfence();
        int d = atomicAdd(&g_done_gates, 1);
        s_last = (d == (int)gridDim.x - 1);
        if (s_last) g_done_gates = 0;
    }
    __syncthreads();
    if (s_last) {
        for (int j = t; j < CTRLD; j += 128) {
            float ig = g_gates[j], fg = g_gates[CTRLD + j], gg = g_gates[2 * CTRLD + j];
            g_ctrl[j] = sigmoidf(fg) * prev_c[j] + sigmoidf(ig) * tanhf(gg);
            g_reads[j] = 0.f;
        }
        if (t < 32) g_S[t] = 0.f;
    }
}

// ---------------- 2) head FCs + (last block) derive keys/scalars ----------------
__global__ void __launch_bounds__(128) k_headfc(
    const float* __restrict__ Ww, const float* __restrict__ bw,
    const float* __restrict__ Wr, const float* __restrict__ br) {
    int row = blockIdx.x;              // 0..4143
    int hd = row / 1036, k = row % 1036;
    const float* wrow; float bias;
    if (k < 774) { wrow = Ww + ((size_t)hd * 774 + k) * CTRLD; bias = bw[hd * 774 + k]; }
    else         { int kk = k - 774; wrow = Wr + ((size_t)hd * 262 + kk) * CTRLD; bias = br[hd * 262 + kk]; }
    const float4* w4 = (const float4*)wrow;
    const float4* c4 = (const float4*)g_ctrl;
    int t = threadIdx.x; float s = 0.f;
#pragma unroll 2
    for (int j = t; j < 256; j += 128) { float4 a = w4[j], v = c4[j]; s += a.x*v.x + a.y*v.y + a.z*v.z + a.w*v.w; }
    s = blockSum(s);
    __shared__ int s_last;
    if (t == 0) {
        g_o[row] = s + bias;
        __threadfence();
        int d = atomicAdd(&g_done_fc, 1);
        s_last = (d == (int)gridDim.x - 1);
        if (s_last) g_done_fc = 0;
    }
    __syncthreads();
    if (s_last) {
        for (int b = 0; b < 8; b++) {
            int hh = b >> 1, role = b & 1;
            const float* o = g_o + hh * 1036 + (role ? 774 : 0);
            float ssl = 0.f;
            for (int j = t; j < Mm; j += 128) {
                float kv = tanhf(o[j]);
                (role ? g_kr : g_kw)[hh * Mm + j] = kv;
                ssl += kv * kv;
                if (!role) {
                    g_e[hh * Mm + j] = sigmoidf(o[262 + j]);
                    g_a[hh * Mm + j] = tanhf(o[518 + j]);
                }
            }
            float ss = blockSum(ssl);
            if (t == 0) {
                float* sc = g_sc + b * 8;
                sc[0] = softplusf(o[256]);
                sc[1] = sigmoidf(o[257]);
                float s0 = o[258], s1 = o[259], s2 = o[260];
                float mx = fmaxf(s0, fmaxf(s1, s2));
                float e0 = expf(s0 - mx), e1 = expf(s1 - mx), e2 = expf(s2 - mx);
                float es = e0 + e1 + e2;
                sc[2] = e0 / es; sc[3] = e1 / es; sc[4] = e2 / es;
                sc[5] = 1.f + softplusf(o[261]);
                sc[6] = sqrtf(ss);
            }
        }
    }
}

// ---------------- addressing phase (read role hr, write role hw; -1 = skip) -----
__device__ __forceinline__ void addr_phase(int b, int t, int hr, int hw,
                                           const float* __restrict__ prev_rw,
                                           const float* __restrict__ prev_ww) {
    float sumr = 0.f, sumw = 0.f;
    if (t < ROWS_B) {
        int i = b * ROWS_B + t;
        int ip = (i + 1) & (Nn - 1), im = (i - 1) & (Nn - 1);
        if (hr >= 0) {
            const float* sc = g_sc + (hr * 2 + 1) * 8;
            float beta = sc[0], gg = sc[1], c0 = sc[2], c1 = sc[3], c2 = sc[4], gamma = sc[5];
            float gS = gg / __ldcg(&g_S[hr * 4 + 2]);
            float om = 1.f - gg;
            const float* pw = prev_rw + (size_t)hr * Nn;
            float wgp = gS * expf(beta * __ldcg(&g_simr[ip])) + om * pw[ip];
            float wgc = gS * expf(beta * __ldcg(&g_simr[i]))  + om * pw[i];
            float wgm = gS * expf(beta * __ldcg(&g_simr[im])) + om * pw[im];
            float ws = c0 * wgp + c1 * wgc + c2 * wgm;
            float wsh = powf(fmaxf(ws, 1e-12f), gamma);
            g_wshr[i] = wsh; sumr = wsh;
        }
        if (hw >= 0) {
            const float* sc = g_sc + (hw * 2) * 8;
            float beta = sc[0], gg = sc[1], c0 = sc[2], c1 = sc[3], c2 = sc[4], gamma = sc[5];
            float gS = gg / __ldcg(&g_S[hw * 4 + 0]);
            float om = 1.f - gg;
            const float* pw = prev_ww + (size_t)hw * Nn;
            float wgp = gS * expf(beta * __ldcg(&g_simw[ip])) + om * pw[ip];
            float wgc = gS * expf(beta * __ldcg(&g_simw[i]))  + om * pw[i];
            float wgm = gS * expf(beta * __ldcg(&g_simw[im])) + om * pw[im];
            float ws = c0 * wgp + c1 * wgc + c2 * wgm;
            float wsh = powf(fmaxf(ws, 1e-12f), gamma);
            g_wshw[i] = wsh; sumw = wsh;
        }
    }
    sumr = blockSum(sumr);
    if (t == 0 && hr >= 0) atomicAdd(&g_S[hr * 4 + 3], sumr);
    sumw = blockSum(sumw);
    if (t == 0 && hw >= 0) atomicAdd(&g_S[hw * 4 + 1], sumw);
}

// ---------------- 3) persistent memory pipeline ----------------------------------
__global__ void __launch_bounds__(PBLK, 4) k_persist(
    const float* __restrict__ mem_in,
    const float* __restrict__ prev_rw,
    const float* __restrict__ prev_ww) {
    __shared__ float s_e[Mm], s_a[Mm], s_kr[Mm], s_kw[Mm];
    __shared__ float s_acc[Mm];
    __shared__ float s_red[16];
    __shared__ unsigned long long s_base;
    const int b = blockIdx.x, t = threadIdx.x, lane = t & 31, wrp = t >> 5;
    const int r0 = b * ROWS_B;

    if (t == 0) s_base = *(volatile unsigned long long*)&g_barcnt;
    s_kw[t] = g_kw[t];   // head-0 write key
    __syncthreads();
    const unsigned long long base = s_base;

    // ---- pass0: sim for head-0 write key ----
    {
        float beta = g_sc[0], kn = g_sc[6];
        float ess = 0.f;
        const float4* k4 = (const float4*)s_kw;
        for (int k = 0; k < ROWS_W; k++) {
            int r = r0 + wrp * ROWS_W + k;
            const float4* row = (const float4*)(mem_in + (size_t)r * Mm);
            float dot = 0.f, ss = 0.f;
#pragma unroll
            for (int j = 0; j < 2; j++) {
                int idx = lane + 32 * j;
                float4 m = row[idx], kk = k4[idx];
                dot += m.x*kk.x + m.y*kk.y + m.z*kk.z + m.w*kk.w;
                ss  += m.x*m.x + m.y*m.y + m.z*m.z + m.w*m.w;
            }
            dot = warpSum(dot); ss = warpSum(ss);
            if (lane == 0) {
                float sim = dot / (sqrtf(ss) * kn + EPSF);
                g_simw[r] = sim;
                ess += expf(beta * sim);
            }
        }
        if (lane == 0) s_red[wrp] = ess;
        __syncthreads();
        if (t == 0) { float s = 0.f; for (int w = 0; w < 8; w++) s += s_red[w]; atomicAdd(&g_S[0], s); }
    }
    gridbar(base, 1);
    addr_phase(b, t, -1, 0, prev_rw, prev_ww);   // write-addressing head 0
    gridbar(base, 2);

    for (int hd = 0; hd < 4; hd++) {
        // ---- update[hd] (+ reads[hd-1] accumulation) ----
        __syncthreads();
        s_e[t]  = g_e[hd * Mm + t];
        s_a[t]  = g_a[hd * Mm + t];
        s_kr[t] = g_kr[hd * Mm + t];
        s_kw[t] = g_kw[((hd + 1) & 3) * Mm + t];
        s_acc[t] = 0.f;
        __syncthreads();
        float invS2w  = 1.f / (__ldcg(&g_S[hd * 4 + 1]) + EPSF);
        float invS2rp = (hd > 0) ? 1.f / (__ldcg(&g_S[(hd - 1) * 4 + 3]) + EPSF) : 0.f;
        float beta_r = g_sc[(hd * 2 + 1) * 8 + 0], kn_r = g_sc[(hd * 2 + 1) * 8 + 6];
        float beta_w = g_sc[((hd + 1) * 2) * 8 + 0], kn_w = g_sc[((hd + 1) * 2) * 8 + 6];
        const float* src = (hd == 0) ? mem_in : g_mem;
        float4 racc0 = make_float4(0, 0, 0, 0), racc1 = make_float4(0, 0, 0, 0);
        float er = 0.f, ew = 0.f;
        const float4* e4  = (const float4*)s_e;
        const float4* a4  = (const float4*)s_a;
        const float4* kr4 = (const float4*)s_kr;
        const float4* kw4 = (const float4*)s_kw;
        for (int k = 0; k < ROWS_W; k++) {
            int r = r0 + wrp * ROWS_W + k;
            float w  = g_wshw[r] * invS2w;
            float wp = (hd > 0) ? g_wshr[r] * invS2rp : 0.f;
            const float4* row = (const float4*)(src + (size_t)r * Mm);
            float4* dst = (float4*)(g_mem + (size_t)r * Mm);
            float dr = 0.f, dw = 0.f, ss = 0.f;
#pragma unroll
            for (int j = 0; j < 2; j++) {
                int idx = lane + 32 * j;
                float4 m = row[idx];
                float4 ee = e4[idx], aa = a4[idx];
                float4 nm;
                nm.x = m.x * (1.f - w * ee.x) + w * aa.x;
                nm.y = m.y * (1.f - w * ee.y) + w * aa.y;
                nm.z = m.z * (1.f - w * ee.z) + w * aa.z;
                nm.w = m.w * (1.f - w * ee.w) + w * aa.w;
                dst[idx] = nm;
                if (j == 0) { racc0.x += wp*m.x; racc0.y += wp*m.y; racc0.z += wp*m.z; racc0.w += wp*m.w; }
                else        { racc1.x += wp*m.x; racc1.y += wp*m.y; racc1.z += wp*m.z; racc1.w += wp*m.w; }
                float4 kr = kr4[idx];
                dr += nm.x*kr.x + nm.y*kr.y + nm.z*kr.z + nm.w*kr.w;
                ss += nm.x*nm.x + nm.y*nm.y + nm.z*nm.z + nm.w*nm.w;
                float4 kw = kw4[idx];
                dw += nm.x*kw.x + nm.y*kw.y + nm.z*kw.z + nm.w*kw.w;
            }
            dr = warpSum(dr); ss = warpSum(ss); dw = warpSum(dw);
            if (lane == 0) {
                float nrm = sqrtf(ss);
                float simr = dr / (nrm * kn_r + EPSF);
                g_simr[r] = simr;
                er += expf(beta_r * simr);
                if (hd < 3) {
                    float simw = dw / (nrm * kn_w + EPSF);
                    g_simw[r] = simw;
                    ew += expf(beta_w * simw);
                }
            }
        }
        if (lane == 0) { s_red[wrp] = er; s_red[8 + wrp] = ew; }
        if (hd > 0) {
            atomicAdd(&s_acc[4 * lane + 0], racc0.x);
            atomicAdd(&s_acc[4 * lane + 1], racc0.y);
            atomicAdd(&s_acc[4 * lane + 2], racc0.z);
            atomicAdd(&s_acc[4 * lane + 3], racc0.w);
            atomicAdd(&s_acc[128 + 4 * lane + 0], racc1.x);
            atomicAdd(&s_acc[128 + 4 * lane + 1], racc1.y);
            atomicAdd(&s_acc[128 + 4 * lane + 2], racc1.z);
            atomicAdd(&s_acc[128 + 4 * lane + 3], racc1.w);
        }
        __syncthreads();
        if (t == 0) {
            float sr = 0.f, sw = 0.f;
            for (int w2 = 0; w2 < 8; w2++) { sr += s_red[w2]; sw += s_red[8 + w2]; }
            atomicAdd(&g_S[hd * 4 + 2], sr);
            if (hd < 3) atomicAdd(&g_S[(hd + 1) * 4 + 0], sw);
        }
        if (hd > 0) atomicAdd(&g_reads[(hd - 1) * Mm + t], s_acc[t]);
        gridbar(base, 3 + 2 * hd);
        addr_phase(b, t, hd, (hd < 3) ? hd + 1 : -1, prev_rw, prev_ww);
        gridbar(base, 4 + 2 * hd);
    }

    // ---- final: reads[3] = rw3 @ mem ----
    {
        float invS2r = 1.f / (__ldcg(&g_S[15]) + EPSF);
        s_acc[t] = 0.f;
        __syncthreads();
        float4 racc0 = make_float4(0, 0, 0, 0), racc1 = make_float4(0, 0, 0, 0);
        for (int k = 0; k < ROWS_W; k++) {
            int r = r0 + wrp * ROWS_W + k;
            float w = g_wshr[r] * invS2r;
            const float4* row = (const float4*)(g_mem + (size_t)r * Mm);
#pragma unroll
            for (int j = 0; j < 2; j++) {
                int idx = lane + 32 * j;
                float4 m = row[idx];
                if (j == 0) { racc0.x += w*m.x; racc0.y += w*m.y; racc0.z += w*m.z; racc0.w += w*m.w; }
                else        { racc1.x += w*m.x; racc1.y += w*m.y; racc1.z += w*m.z; racc1.w += w*m.w; }
            }
        }
        atomicAdd(&s_acc[4 * lane + 0], racc0.x);
        atomicAdd(&s_acc[4 * lane + 1], racc0.y);
        atomicAdd(&s_acc[4 * lane + 2], racc0.z);
        atomicAdd(&s_acc[4 * lane + 3], racc0.w);
        atomicAdd(&s_acc[128 + 4 * lane + 0], racc1.x);
        atomicAdd(&s_acc[128 + 4 * lane + 1], racc1.y);
        atomicAdd(&s_acc[128 + 4 * lane + 2], racc1.z);
        atomicAdd(&s_acc[128 + 4 * lane + 3], racc1.w);
        __syncthreads();
        atomicAdd(&g_reads[3 * Mm + t], s_acc[t]);
    }
}

// ---------------- 4) output GEMV --------------------------------------------------
__global__ void __launch_bounds__(128) k_out(
    const float* __restrict__ W_out, const float* __restrict__ b_out,
    float* __restrict__ out) {
    int row = blockIdx.x, t = threadIdx.x;
    const float4* w4 = (const float4*)(W_out + (size_t)row * (Hh * Mm));
    const float4* r4 = (const float4*)g_reads;
    float s = 0.f;
#pragma unroll 2
    for (int j = t; j < 256; j += 128) { float4 a = w4[j], v = r4[j]; s += a.x*v.x + a.y*v.y + a.z*v.z + a.w*v.w; }
    s = blockSum(s);
    if (t == 0) out[row] = s + b_out[row];
}

// ---------------- launch -----------------------------------------------------------
extern "C" void kernel_launch(void* const* d_in, const int* in_sizes, int n_in,
                              void* d_out, int out_size) {
    const float* x          = (const float*)d_in[0];
    const float* prev_reads = (const float*)d_in[1];
    const float* prev_h     = (const float*)d_in[2];
    const float* prev_c     = (const float*)d_in[3];
    const float* memory     = (const float*)d_in[4];
    const float* prev_rw    = (const float*)d_in[5];
    const float* prev_ww    = (const float*)d_in[6];
    const float* W_ih       = (const float*)d_in[7];
    const float* W_hh       = (const float*)d_in[8];
    const float* b_lstm     = (const float*)d_in[9];
    const float* W_out      = (const float*)d_in[10];
    const float* b_out      = (const float*)d_in[11];
    const float* Ww         = (const float*)d_in[12];
    const float* bw         = (const float*)d_in[13];
    const float* Wr         = (const float*)d_in[14];
    const float* br         = (const float*)d_in[15];
    float* out = (float*)d_out;

    k_gates  <<<3072, 128>>>(x, prev_reads, prev_h, prev_c, W_ih, W_hh, b_lstm);
    k_headfc <<<4144, 128>>>(Ww, bw, Wr, br);
    k_persist<<<PGRID, PBLK>>>(memory, prev_rw, prev_ww);
    k_out    <<<OUTD, 128>>>(W_out, b_out, out);
}